// round 1
// baseline (speedup 1.0000x reference)
#include <cuda_runtime.h>
#include <math.h>

#define BSZ 256        // batch B
#define KS 16          // n_z_samples
#define NSEQ 4096      // K*B
#define H 64
#define G4 256         // 4*H
#define ZXD 320
#define LSTM_IN 322
#define TT 50
#define GC 16

// scratch (static device allocs are allowed)
__device__ float g_G0[NSEQ * G4];
__device__ float g_h0[NSEQ * H];
__device__ float g_c0[NSEQ * H];

// ---------------------------------------------------------------------------
// Phase 1:  C[N,384] = zx[N,320] @ W^T   where W rows are:
//   cols   0..255 : Wih[:, :320]   -> G0  (+ bih + bhh)
//   cols 256..319 : Wh0            -> h0  (+ bh0)
//   cols 320..383 : Wc0            -> c0  (+ bc0)
// zx[n] = concat(z_flat[n] (64), x[n % B] (256))
// ---------------------------------------------------------------------------
__global__ __launch_bounds__(256) void phase1_kernel(
    const float* __restrict__ x, const float* __restrict__ z,
    const float* __restrict__ Wih, const float* __restrict__ Wh0,
    const float* __restrict__ Wc0,
    const float* __restrict__ bih, const float* __restrict__ bhh,
    const float* __restrict__ bh0, const float* __restrict__ bc0)
{
    __shared__ float As[16][68];
    __shared__ float Ws[16][68];
    const int tid = threadIdx.x;
    const int n0 = blockIdx.x * 64;
    const int c0 = blockIdx.y * 64;
    const int tx = tid & 15, ty = tid >> 4;
    float acc[4][4] = {};

    for (int kt = 0; kt < ZXD; kt += 16) {
        // A tile: half-warps read 16 consecutive k (coalesced 64B)
        #pragma unroll
        for (int i = 0; i < 4; i++) {
            int e = tid + i * 256;
            int kk = e & 15, rr = e >> 4;
            int n = n0 + rr, m = kt + kk;
            float v = (m < H) ? z[n * H + m]
                              : x[(n & (BSZ - 1)) * 256 + (m - H)];
            As[kk][rr] = v;
        }
        // W tile
        #pragma unroll
        for (int i = 0; i < 4; i++) {
            int e = tid + i * 256;
            int kk = e & 15, cc = e >> 4;
            int j = c0 + cc, m = kt + kk;
            float v;
            if (j < G4)          v = Wih[j * LSTM_IN + m];
            else if (j < G4 + H) v = Wh0[(j - G4) * ZXD + m];
            else                 v = Wc0[(j - G4 - H) * ZXD + m];
            Ws[kk][cc] = v;
        }
        __syncthreads();
        #pragma unroll
        for (int kk = 0; kk < 16; kk++) {
            float a[4], b[4];
            #pragma unroll
            for (int i = 0; i < 4; i++) a[i] = As[kk][ty * 4 + i];
            #pragma unroll
            for (int j = 0; j < 4; j++) b[j] = Ws[kk][tx * 4 + j];
            #pragma unroll
            for (int i = 0; i < 4; i++)
                #pragma unroll
                for (int j = 0; j < 4; j++)
                    acc[i][j] += a[i] * b[j];
        }
        __syncthreads();
    }

    #pragma unroll
    for (int i = 0; i < 4; i++) {
        int n = n0 + ty * 4 + i;
        #pragma unroll
        for (int j = 0; j < 4; j++) {
            int col = c0 + tx * 4 + j;
            float v = acc[i][j];
            if (col < G4)          g_G0[n * G4 + col]          = v + bih[col] + bhh[col];
            else if (col < G4 + H) g_h0[n * H + (col - G4)]     = v + bh0[col - G4];
            else                   g_c0[n * H + (col - G4 - H)] = v + bc0[col - G4 - H];
        }
    }
}

// ---------------------------------------------------------------------------
// Phase 2: persistent recurrence + heads + GMM.  128 blocks x 32 seqs.
// ---------------------------------------------------------------------------
#define WG_STRIDE 264   // Whh^T row stride (floats)
#define WP_STRIDE 104   // head weight row stride
#define HS_STRIDE 73    // h tile row stride

#define SM_WG   0
#define SM_WP   (SM_WG + 64 * WG_STRIDE)
#define SM_WD   (SM_WP + 64 * WP_STRIDE)
#define SM_BH   (SM_WD + 2 * 256)
#define SM_HS   (SM_BH + 96)
#define SM_PO   (SM_HS + 32 * HS_STRIDE)
#define SM_C1   (SM_PO + 32 * WP_STRIDE)
#define SM_DDE  (SM_C1 + 32 * 16)
#define SM_TOT  (SM_DDE + 64)
#define SMEM_BYTES (SM_TOT * 4)

__global__ __launch_bounds__(256) void phase2_kernel(
    const float* __restrict__ inp_seqs, const float* __restrict__ pred_seqs,
    const float* __restrict__ Whh, const float* __restrict__ Wih,
    const float* __restrict__ Wpi, const float* __restrict__ bpi,
    const float* __restrict__ Wmu, const float* __restrict__ bmu,
    const float* __restrict__ Wls, const float* __restrict__ bls,
    const float* __restrict__ Wcorr, const float* __restrict__ bcorr,
    float* __restrict__ out)
{
    extern __shared__ float sm[];
    float* Wg  = sm + SM_WG;   // [64][264]  Wg[k][g] = Whh[g][k]
    float* Wp  = sm + SM_WP;   // [64][104]  head weights^T
    float* Wd  = sm + SM_WD;   // [2][256]   Wih cols 320,321
    float* bh  = sm + SM_BH;   // [96]
    float* Hs  = sm + SM_HS;   // [32][73]
    float* Po  = sm + SM_PO;   // [32][104]  head outputs
    float* C1  = sm + SM_C1;   // [32][16]   pi + comp
    float* Dde = sm + SM_DDE;  // [32][2]

    const int tid = threadIdx.x;
    const int nb  = blockIdx.x * 32;

    // ---- stage weights ----
    for (int e = tid; e < 64 * 256; e += 256) {
        int g = e & 255, k = e >> 8;
        Wg[k * WG_STRIDE + g] = Whh[g * 64 + k];
    }
    for (int e = tid; e < 64 * 96; e += 256) {
        int j = e % 96, k = e / 96;
        float v;
        if (j < 16)      v = Wpi[j * 64 + k];
        else if (j < 48) v = Wmu[(j - 16) * 64 + k];
        else if (j < 80) v = Wls[(j - 48) * 64 + k];
        else             v = Wcorr[(j - 80) * 64 + k];
        Wp[k * WP_STRIDE + j] = v;
    }
    for (int e = tid; e < 512; e += 256) {
        int d = e >> 8, g = e & 255;
        Wd[d * 256 + g] = Wih[g * LSTM_IN + 320 + d];
    }
    if (tid < 96) {
        int j = tid; float v;
        if (j < 16)      v = bpi[j];
        else if (j < 48) v = bmu[j - 16];
        else if (j < 80) v = bls[j - 48];
        else             v = bcorr[j - 80];
        bh[j] = v;
    }

    // ---- per-thread register state ----
    const int s0 = tid >> 4;          // 0..15 ; owns seqs {s0, s0+16}
    const int u0 = (tid & 15) * 4;    // hidden units u0..u0+3
    const int n_a = nb + s0, n_b = nb + s0 + 16;

    float G0r[2][16];  // [seq][u*4+q]
    float cr[2][4];
    #pragma unroll
    for (int u = 0; u < 4; u++) {
        cr[0][u] = g_c0[n_a * H + u0 + u];
        cr[1][u] = g_c0[n_b * H + u0 + u];
        Hs[s0 * HS_STRIDE + u0 + u]        = g_h0[n_a * H + u0 + u];
        Hs[(s0 + 16) * HS_STRIDE + u0 + u] = g_h0[n_b * H + u0 + u];
        #pragma unroll
        for (int q = 0; q < 4; q++) {
            G0r[0][u * 4 + q] = g_G0[n_a * G4 + q * 64 + u0 + u];
            G0r[1][u * 4 + q] = g_G0[n_b * G4 + q * 64 + u0 + u];
        }
    }

    // decode input for first step (t=1, scan index 0 -> tgt_present)
    if (tid < 64) {
        int s = tid >> 1, d = tid & 1;
        int b = (nb + s) & (BSZ - 1);
        Dde[s * 2 + d] = inp_seqs[(b * 8 + 7) * 24 + 20 + d];
    }
    float lacc = 0.f;  // used by tid < 32
    __syncthreads();

    for (int t = 1; t <= TT; t++) {
        // ---- gates GEMM: acc = G0 + d.Wd + h_{t-1} @ Whh^T ----
        float acc[2][16];
        {
            float dxa = Dde[s0 * 2], dya = Dde[s0 * 2 + 1];
            float dxb = Dde[(s0 + 16) * 2], dyb = Dde[(s0 + 16) * 2 + 1];
            #pragma unroll
            for (int u = 0; u < 4; u++)
                #pragma unroll
                for (int q = 0; q < 4; q++) {
                    int g = q * 64 + u0 + u;
                    acc[0][u * 4 + q] = G0r[0][u * 4 + q] + dxa * Wd[g] + dya * Wd[256 + g];
                    acc[1][u * 4 + q] = G0r[1][u * 4 + q] + dxb * Wd[g] + dyb * Wd[256 + g];
                }
        }
        #pragma unroll 4
        for (int k = 0; k < 64; k++) {
            float ha = Hs[s0 * HS_STRIDE + k];
            float hb = Hs[(s0 + 16) * HS_STRIDE + k];
            #pragma unroll
            for (int q = 0; q < 4; q++) {
                float4 w = *(const float4*)&Wg[k * WG_STRIDE + q * 64 + u0];
                acc[0][0 * 4 + q] += ha * w.x;
                acc[0][1 * 4 + q] += ha * w.y;
                acc[0][2 * 4 + q] += ha * w.z;
                acc[0][3 * 4 + q] += ha * w.w;
                acc[1][0 * 4 + q] += hb * w.x;
                acc[1][1 * 4 + q] += hb * w.y;
                acc[1][2 * 4 + q] += hb * w.z;
                acc[1][3 * 4 + q] += hb * w.w;
            }
        }
        __syncthreads();  // everyone done reading Hs (and Dde)

        // ---- pointwise LSTM update (all in registers) ----
        #pragma unroll
        for (int s = 0; s < 2; s++) {
            #pragma unroll
            for (int u = 0; u < 4; u++) {
                float gi = acc[s][u * 4 + 0];
                float gf = acc[s][u * 4 + 1];
                float gg = acc[s][u * 4 + 2];
                float go = acc[s][u * 4 + 3];
                float si = 1.f / (1.f + __expf(-gi));
                float sf = 1.f / (1.f + __expf(-gf));
                float so = 1.f / (1.f + __expf(-go));
                float c  = sf * cr[s][u] + si * tanhf(gg);
                cr[s][u] = c;
                float hv = so * tanhf(c);
                Hs[(s0 + s * 16) * HS_STRIDE + u0 + u] = hv;
            }
        }
        // decode input for next step (scan index t -> tgt_future[t-1])
        if (t < TT && tid < 64) {
            int s = tid >> 1, d = tid & 1;
            int b = (nb + s) & (BSZ - 1);
            Dde[s * 2 + d] = pred_seqs[(b * TT + (t - 1)) * 24 + 20 + d];
        }
        __syncthreads();  // new Hs + next Dde visible

        // ---- heads GEMM: Po[32][96] = h_t @ Wheads^T + b ----
        {
            int hs = tid >> 3;              // seq 0..31
            int j0 = (tid & 7) * 12;        // 12 head cols
            float ha[12];
            #pragma unroll
            for (int jj = 0; jj < 12; jj++) ha[jj] = bh[j0 + jj];
            #pragma unroll 4
            for (int k = 0; k < 64; k++) {
                float h = Hs[hs * HS_STRIDE + k];
                const float* wr = &Wp[k * WP_STRIDE + j0];
                float4 w0 = *(const float4*)(wr);
                float4 w1 = *(const float4*)(wr + 4);
                float4 w2 = *(const float4*)(wr + 8);
                ha[0]  += h * w0.x; ha[1]  += h * w0.y; ha[2]  += h * w0.z; ha[3]  += h * w0.w;
                ha[4]  += h * w1.x; ha[5]  += h * w1.y; ha[6]  += h * w1.z; ha[7]  += h * w1.w;
                ha[8]  += h * w2.x; ha[9]  += h * w2.y; ha[10] += h * w2.z; ha[11] += h * w2.w;
            }
            #pragma unroll
            for (int jj = 0; jj < 12; jj++) Po[hs * WP_STRIDE + j0 + jj] = ha[jj];
        }
        __syncthreads();

        // ---- GMM components ----
        {
            int s = tid >> 3;
            int b = (nb + s) & (BSZ - 1);
            const float* tg = &pred_seqs[(b * TT + (t - 1)) * 24 + 20];
            float txv = tg[0], tyv = tg[1];
            int cbase = (tid & 7) * 2;
            #pragma unroll
            for (int cc = 0; cc < 2; cc++) {
                int c = cbase + cc;
                const float* pr = &Po[s * WP_STRIDE];
                float pi  = pr[c];
                float mu0 = pr[16 + 2 * c], mu1 = pr[17 + 2 * c];
                float ls0 = fminf(fmaxf(pr[48 + 2 * c], -10.f), 10.f);
                float ls1 = fminf(fmaxf(pr[49 + 2 * c], -10.f), 10.f);
                float corr = tanhf(pr[80 + c]);
                float dx = txv - mu0, dy = tyv - mu1;
                float z0 = dx * __expf(-ls0);
                float z1 = dy * __expf(-ls1);
                float omr  = 1.f - corr * corr;
                float quad = z0 * z0 + z1 * z1 - 2.f * corr * z0 * z1;
                float cv = -1.8378770664093453f - (ls0 + ls1)
                           - 0.5f * __logf(omr) - 0.5f * quad / omr;
                C1[s * 16 + c] = pi + cv;
            }
        }
        __syncthreads();

        // ---- logsumexp + accumulate (one thread per sequence) ----
        if (tid < 32) {
            int s = tid;
            const float* pr = &Po[s * WP_STRIDE];
            const float* cr1 = &C1[s * 16];
            float m1 = -1e30f, m2 = -1e30f;
            #pragma unroll
            for (int c = 0; c < 16; c++) {
                m1 = fmaxf(m1, pr[c]);
                m2 = fmaxf(m2, cr1[c]);
            }
            float sm1 = 0.f, sm2 = 0.f;
            #pragma unroll
            for (int c = 0; c < 16; c++) {
                sm1 += __expf(pr[c] - m1);
                sm2 += __expf(cr1[c] - m2);
            }
            float lp = (m2 + __logf(sm2)) - (m1 + __logf(sm1));
            lacc += fminf(lp, 50.f);
        }
        // no trailing barrier needed: next writes to Po/C1 happen only after
        // two more __syncthreads in the next iteration.
    }

    if (tid < 32) out[nb + tid] = lacc;
}

// ---------------------------------------------------------------------------
extern "C" void kernel_launch(void* const* d_in, const int* in_sizes, int n_in,
                              void* d_out, int out_size)
{
    const float* x      = (const float*)d_in[0];
    const float* z      = (const float*)d_in[1];
    const float* inps   = (const float*)d_in[2];
    const float* preds  = (const float*)d_in[3];
    const float* Wh0    = (const float*)d_in[4];
    const float* bh0    = (const float*)d_in[5];
    const float* Wc0    = (const float*)d_in[6];
    const float* bc0    = (const float*)d_in[7];
    const float* Wih    = (const float*)d_in[8];
    const float* Whh    = (const float*)d_in[9];
    const float* bih    = (const float*)d_in[10];
    const float* bhh    = (const float*)d_in[11];
    const float* Wpi    = (const float*)d_in[12];
    const float* bpi    = (const float*)d_in[13];
    const float* Wmu    = (const float*)d_in[14];
    const float* bmu    = (const float*)d_in[15];
    const float* Wls    = (const float*)d_in[16];
    const float* bls    = (const float*)d_in[17];
    const float* Wcorr  = (const float*)d_in[18];
    const float* bcorr  = (const float*)d_in[19];
    float* out = (float*)d_out;

    cudaFuncSetAttribute(phase2_kernel,
                         cudaFuncAttributeMaxDynamicSharedMemorySize, SMEM_BYTES);

    dim3 g1(NSEQ / 64, 384 / 64);
    phase1_kernel<<<g1, 256>>>(x, z, Wih, Wh0, Wc0, bih, bhh, bh0, bc0);

    phase2_kernel<<<NSEQ / 32, 256, SMEM_BYTES>>>(
        inps, preds, Whh, Wih,
        Wpi, bpi, Wmu, bmu, Wls, bls, Wcorr, bcorr, out);
}

// round 2
// speedup vs baseline: 1.3436x; 1.3436x over previous
#include <cuda_runtime.h>
#include <math.h>

#define BSZ 256        // batch B
#define NSEQ 4096      // K*B
#define H 64
#define G4 256         // 4*H
#define ZXD 320
#define LSTM_IN 322
#define TT 50

typedef unsigned long long ull;

// packed f32x2 helpers (ptxas never auto-fuses; PTX-only path)
#define FMA2(d, a, b, c) asm("fma.rn.f32x2 %0, %1, %2, %3;" : "=l"(d) : "l"(a), "l"(b), "l"(c))
#define PACKF2(d, x, y)  asm("mov.b64 %0, {%1, %2};" : "=l"(d) : "f"(x), "f"(y))
#define UNPACKF2(x, y, d) asm("mov.b64 {%0, %1}, %2;" : "=f"(x), "=f"(y) : "l"(d))

__device__ __forceinline__ float sigf(float x) {
    return __fdividef(1.f, 1.f + __expf(-x));
}
__device__ __forceinline__ float tanh_fast(float x) {
    // tanh(x) = 1 - 2/(exp(2x)+1); saturates correctly at +/-inf
    return 1.f - __fdividef(2.f, __expf(2.f * x) + 1.f);
}

// scratch
__device__ float g_G0[NSEQ * G4];   // interleaved: [n][u*4+q]
__device__ float g_h0[NSEQ * H];
__device__ float g_c0[NSEQ * H];

// ---------------------------------------------------------------------------
// Phase 1:  [G0 | h0 | c0] = zx @ [Wih[:, :320] | Wh0 | Wc0]^T  (+ biases)
// G0 written in unit-interleaved layout: g_G0[n*256 + u*4 + q]
// ---------------------------------------------------------------------------
__global__ __launch_bounds__(256) void phase1_kernel(
    const float* __restrict__ x, const float* __restrict__ z,
    const float* __restrict__ Wih, const float* __restrict__ Wh0,
    const float* __restrict__ Wc0,
    const float* __restrict__ bih, const float* __restrict__ bhh,
    const float* __restrict__ bh0, const float* __restrict__ bc0)
{
    __shared__ float As[16][68];
    __shared__ float Ws[16][68];
    const int tid = threadIdx.x;
    const int n0 = blockIdx.x * 64;
    const int c0 = blockIdx.y * 64;
    const int tx = tid & 15, ty = tid >> 4;
    float acc[4][4] = {};

    for (int kt = 0; kt < ZXD; kt += 16) {
        #pragma unroll
        for (int i = 0; i < 4; i++) {
            int e = tid + i * 256;
            int kk = e & 15, rr = e >> 4;
            int n = n0 + rr, m = kt + kk;
            float v = (m < H) ? z[n * H + m]
                              : x[(n & (BSZ - 1)) * 256 + (m - H)];
            As[kk][rr] = v;
        }
        #pragma unroll
        for (int i = 0; i < 4; i++) {
            int e = tid + i * 256;
            int kk = e & 15, cc = e >> 4;
            int j = c0 + cc, m = kt + kk;
            float v;
            if (j < G4)          v = Wih[j * LSTM_IN + m];
            else if (j < G4 + H) v = Wh0[(j - G4) * ZXD + m];
            else                 v = Wc0[(j - G4 - H) * ZXD + m];
            Ws[kk][cc] = v;
        }
        __syncthreads();
        #pragma unroll
        for (int kk = 0; kk < 16; kk++) {
            float a[4], b[4];
            #pragma unroll
            for (int i = 0; i < 4; i++) a[i] = As[kk][ty * 4 + i];
            #pragma unroll
            for (int j = 0; j < 4; j++) b[j] = Ws[kk][tx * 4 + j];
            #pragma unroll
            for (int i = 0; i < 4; i++)
                #pragma unroll
                for (int j = 0; j < 4; j++)
                    acc[i][j] += a[i] * b[j];
        }
        __syncthreads();
    }

    #pragma unroll
    for (int i = 0; i < 4; i++) {
        int n = n0 + ty * 4 + i;
        #pragma unroll
        for (int j = 0; j < 4; j++) {
            int col = c0 + tx * 4 + j;
            float v = acc[i][j];
            if (col < G4) {
                int u = col & 63, q = col >> 6;
                g_G0[n * G4 + u * 4 + q] = v + bih[col] + bhh[col];
            }
            else if (col < G4 + H) g_h0[n * H + (col - G4)]     = v + bh0[col - G4];
            else                   g_c0[n * H + (col - G4 - H)] = v + bc0[col - G4 - H];
        }
    }
}

// ---------------------------------------------------------------------------
// Phase 2: persistent recurrence.  128 blocks x 32 seqs x 256 threads.
// lane = sequence (0..31); warp = output slice (8 warps).
// All weight reads are full-warp broadcasts; h reads are conflict-free.
// ---------------------------------------------------------------------------
#define HS_STRIDE 65
#define PO_STRIDE 97

#define SM_WG   0                       // [64][256] interleaved Whh^T
#define SM_WP   (SM_WG + 64 * 256)      // [64][96]  head weights^T
#define SM_WD   (SM_WP + 64 * 96)       // [2][256]  Wih cols 320/321, interleaved
#define SM_BH   (SM_WD + 2 * 256)       // [96]
#define SM_HS   (SM_BH + 96)            // [32][65]
#define SM_PO   (SM_HS + 32 * HS_STRIDE)// [32][97]
#define SM_C1   (SM_PO + 32 * PO_STRIDE)// [32][16]
#define SM_DDE  (SM_C1 + 32 * 16)       // [32][2]
#define SM_TOT  (SM_DDE + 64)
#define SMEM_BYTES (SM_TOT * 4)

__global__ __launch_bounds__(256, 1) void phase2_kernel(
    const float* __restrict__ inp_seqs, const float* __restrict__ pred_seqs,
    const float* __restrict__ Whh, const float* __restrict__ Wih,
    const float* __restrict__ Wpi, const float* __restrict__ bpi,
    const float* __restrict__ Wmu, const float* __restrict__ bmu,
    const float* __restrict__ Wls, const float* __restrict__ bls,
    const float* __restrict__ Wcorr, const float* __restrict__ bcorr,
    float* __restrict__ out)
{
    extern __shared__ float sm[];
    const int tid  = threadIdx.x;
    const int lane = tid & 31;          // sequence within block
    const int warp = tid >> 5;          // output slice
    const int nb   = blockIdx.x * 32;

    // ---- stage weights (once) ----
    // Wg[k][u*4+q] = Whh[(q*64+u)][k]
    for (int e = tid; e < 64 * 256; e += 256) {
        int k = e >> 8, gp = e & 255;
        int u = gp >> 2, q = gp & 3;
        sm[SM_WG + k * 256 + gp] = Whh[(q * 64 + u) * 64 + k];
    }
    // Wp[k][j] head weights transposed
    for (int e = tid; e < 64 * 96; e += 256) {
        int j = e % 96, k = e / 96;
        float v;
        if (j < 16)      v = Wpi[j * 64 + k];
        else if (j < 48) v = Wmu[(j - 16) * 64 + k];
        else if (j < 80) v = Wls[(j - 48) * 64 + k];
        else             v = Wcorr[(j - 80) * 64 + k];
        sm[SM_WP + k * 96 + j] = v;
    }
    // Wd[d][u*4+q]
    for (int e = tid; e < 512; e += 256) {
        int d = e >> 8, gp = e & 255;
        int u = gp >> 2, q = gp & 3;
        sm[SM_WD + d * 256 + gp] = Wih[(q * 64 + u) * LSTM_IN + 320 + d];
    }
    if (tid < 96) {
        int j = tid; float v;
        if (j < 16)      v = bpi[j];
        else if (j < 48) v = bmu[j - 16];
        else if (j < 80) v = bls[j - 48];
        else             v = bcorr[j - 80];
        sm[SM_BH + j] = v;
    }

    // ---- per-thread state: seq = lane, units u in [8*warp, 8*warp+8) ----
    const int n = nb + lane;
    const int u0 = warp * 8;

    ull G0p[16];
    {
        const ull* g0p = (const ull*)g_G0;
        #pragma unroll
        for (int j = 0; j < 16; j++)
            G0p[j] = g0p[n * 128 + warp * 16 + j];
    }
    float cr[8];
    #pragma unroll
    for (int i = 0; i < 8; i++) {
        cr[i] = g_c0[n * H + u0 + i];
        sm[SM_HS + lane * HS_STRIDE + u0 + i] = g_h0[n * H + u0 + i];
    }

    if (tid < 64) {
        int s = tid >> 1, d = tid & 1;
        int b = (nb + s) & (BSZ - 1);
        sm[SM_DDE + s * 2 + d] = inp_seqs[(b * 8 + 7) * 24 + 20 + d];
    }
    float lacc = 0.f;  // warp 0 only
    __syncthreads();

    const float* hrow = sm + SM_HS + lane * HS_STRIDE;

    for (int t = 1; t <= TT; t++) {
        // ---- acc = G0 + dx*Wd0 + dy*Wd1 (packed pairs) ----
        ull acc[16];
        {
            float dxv = sm[SM_DDE + lane * 2];
            float dyv = sm[SM_DDE + lane * 2 + 1];
            ull dx2, dy2;
            PACKF2(dx2, dxv, dxv);
            PACKF2(dy2, dyv, dyv);
            const ulonglong2* wd0 = (const ulonglong2*)(sm + SM_WD + warp * 32);
            const ulonglong2* wd1 = (const ulonglong2*)(sm + SM_WD + 256 + warp * 32);
            #pragma unroll
            for (int i = 0; i < 8; i++) {
                ulonglong2 a = wd0[i], b = wd1[i];
                ull t0, t1;
                FMA2(t0, dx2, a.x, G0p[2 * i]);
                FMA2(acc[2 * i], dy2, b.x, t0);
                FMA2(t1, dx2, a.y, G0p[2 * i + 1]);
                FMA2(acc[2 * i + 1], dy2, b.y, t1);
            }
        }
        // ---- gates GEMM: weight loads broadcast across the warp ----
        #pragma unroll 8
        for (int k = 0; k < 64; k++) {
            float h = hrow[k];
            ull h2; PACKF2(h2, h, h);
            const ulonglong2* wr = (const ulonglong2*)(sm + SM_WG + k * 256 + warp * 32);
            #pragma unroll
            for (int i = 0; i < 8; i++) {
                ulonglong2 w = wr[i];
                FMA2(acc[2 * i],     h2, w.x, acc[2 * i]);
                FMA2(acc[2 * i + 1], h2, w.y, acc[2 * i + 1]);
            }
        }
        __syncthreads();   // done reading Hs / Dde

        // ---- pointwise LSTM update (registers) ----
        #pragma unroll
        for (int i = 0; i < 8; i++) {
            float gi, gf, gg, go;
            UNPACKF2(gi, gf, acc[2 * i]);
            UNPACKF2(gg, go, acc[2 * i + 1]);
            float si = sigf(gi), sf = sigf(gf), so = sigf(go);
            float c = sf * cr[i] + si * tanh_fast(gg);
            cr[i] = c;
            sm[SM_HS + lane * HS_STRIDE + u0 + i] = so * tanh_fast(c);
        }
        if (t < TT && tid < 64) {
            int s = tid >> 1, d = tid & 1;
            int b = (nb + s) & (BSZ - 1);
            sm[SM_DDE + s * 2 + d] = pred_seqs[(b * TT + (t - 1)) * 24 + 20 + d];
        }
        __syncthreads();   // new Hs + next Dde visible

        // ---- heads GEMM: seq = lane, outputs j in [12*warp, 12*warp+12) ----
        {
            ull ph[6];
            const ulonglong2* bhp = (const ulonglong2*)(sm + SM_BH + warp * 12);
            ulonglong2 b0 = bhp[0], b1 = bhp[1], b2 = bhp[2];
            ph[0] = b0.x; ph[1] = b0.y; ph[2] = b1.x;
            ph[3] = b1.y; ph[4] = b2.x; ph[5] = b2.y;
            #pragma unroll 8
            for (int k = 0; k < 64; k++) {
                float h = hrow[k];
                ull h2; PACKF2(h2, h, h);
                const ulonglong2* wp = (const ulonglong2*)(sm + SM_WP + k * 96 + warp * 12);
                ulonglong2 w0 = wp[0], w1 = wp[1], w2 = wp[2];
                FMA2(ph[0], h2, w0.x, ph[0]);
                FMA2(ph[1], h2, w0.y, ph[1]);
                FMA2(ph[2], h2, w1.x, ph[2]);
                FMA2(ph[3], h2, w1.y, ph[3]);
                FMA2(ph[4], h2, w2.x, ph[4]);
                FMA2(ph[5], h2, w2.y, ph[5]);
            }
            float* po = sm + SM_PO + lane * PO_STRIDE + warp * 12;
            #pragma unroll
            for (int p = 0; p < 6; p++) {
                float a, b;
                UNPACKF2(a, b, ph[p]);
                po[2 * p] = a; po[2 * p + 1] = b;
            }
        }
        __syncthreads();   // Po visible

        // ---- GMM components: C1[s][c] = pi_c + log N_c ----
        {
            int s = tid >> 3;
            int b = (nb + s) & (BSZ - 1);
            const float* tg = &pred_seqs[(b * TT + (t - 1)) * 24 + 20];
            float txv = tg[0], tyv = tg[1];
            int cbase = (tid & 7) * 2;
            const float* pr = sm + SM_PO + s * PO_STRIDE;
            #pragma unroll
            for (int cc = 0; cc < 2; cc++) {
                int c = cbase + cc;
                float pi  = pr[c];
                float mu0 = pr[16 + 2 * c], mu1 = pr[17 + 2 * c];
                float ls0 = fminf(fmaxf(pr[48 + 2 * c], -10.f), 10.f);
                float ls1 = fminf(fmaxf(pr[49 + 2 * c], -10.f), 10.f);
                float corr = tanh_fast(pr[80 + c]);
                float dx = txv - mu0, dy = tyv - mu1;
                float z0 = dx * __expf(-ls0);
                float z1 = dy * __expf(-ls1);
                float omr  = 1.f - corr * corr;
                float quad = z0 * z0 + z1 * z1 - 2.f * corr * z0 * z1;
                float cv = -1.8378770664093453f - (ls0 + ls1)
                           - 0.5f * __logf(omr) - 0.5f * __fdividef(quad, omr);
                sm[SM_C1 + s * 16 + c] = pi + cv;
            }
        }
        __syncthreads();   // C1 visible

        // ---- logsumexp + accumulate: one thread per sequence (warp 0) ----
        if (tid < 32) {
            const float* pr = sm + SM_PO + tid * PO_STRIDE;
            const float* c1 = sm + SM_C1 + tid * 16;
            float m1 = -1e30f, m2 = -1e30f;
            #pragma unroll
            for (int c = 0; c < 16; c++) {
                m1 = fmaxf(m1, pr[c]);
                m2 = fmaxf(m2, c1[c]);
            }
            float s1 = 0.f, s2 = 0.f;
            #pragma unroll
            for (int c = 0; c < 16; c++) {
                s1 += __expf(pr[c] - m1);
                s2 += __expf(c1[c] - m2);
            }
            float lp = (m2 + __logf(s2)) - (m1 + __logf(s1));
            lacc += fminf(lp, 50.f);
        }
        // Po/C1 not rewritten until after 2+ barriers next iter -> safe
    }

    if (tid < 32) out[nb + tid] = lacc;
}

// ---------------------------------------------------------------------------
extern "C" void kernel_launch(void* const* d_in, const int* in_sizes, int n_in,
                              void* d_out, int out_size)
{
    const float* x      = (const float*)d_in[0];
    const float* z      = (const float*)d_in[1];
    const float* inps   = (const float*)d_in[2];
    const float* preds  = (const float*)d_in[3];
    const float* Wh0    = (const float*)d_in[4];
    const float* bh0    = (const float*)d_in[5];
    const float* Wc0    = (const float*)d_in[6];
    const float* bc0    = (const float*)d_in[7];
    const float* Wih    = (const float*)d_in[8];
    const float* Whh    = (const float*)d_in[9];
    const float* bih    = (const float*)d_in[10];
    const float* bhh    = (const float*)d_in[11];
    const float* Wpi    = (const float*)d_in[12];
    const float* bpi    = (const float*)d_in[13];
    const float* Wmu    = (const float*)d_in[14];
    const float* bmu    = (const float*)d_in[15];
    const float* Wls    = (const float*)d_in[16];
    const float* bls    = (const float*)d_in[17];
    const float* Wcorr  = (const float*)d_in[18];
    const float* bcorr  = (const float*)d_in[19];
    float* out = (float*)d_out;

    cudaFuncSetAttribute(phase2_kernel,
                         cudaFuncAttributeMaxDynamicSharedMemorySize, SMEM_BYTES);

    dim3 g1(NSEQ / 64, 384 / 64);
    phase1_kernel<<<g1, 256>>>(x, z, Wih, Wh0, Wc0, bih, bhh, bh0, bc0);

    phase2_kernel<<<NSEQ / 32, 256, SMEM_BYTES>>>(
        inps, preds, Whh, Wih,
        Wpi, bpi, Wmu, bmu, Wls, bls, Wcorr, bcorr, out);
}